// round 4
// baseline (speedup 1.0000x reference)
#include <cuda_runtime.h>
#include <math.h>

// Analytic collapse of the product-state quantum circuit:
//   encoded[b,j] = dot(x[b,:], enc_w[j,:]) + enc_b[j]
//   Theta[j]     = sum_{d<4} theta[d*16 + j]
//   m[b,j]       = cos(Theta[j]) * cos(encoded[b,j])
//   logits[b,c]  = sum_j m[b,j]*cls_w[c, 15-j] + cls_b[c]
//
// Grid = 256 (one CTA per batch row), block = 256 (8 warps). Each warp owns
// TWO qubits: lanes 0-15 -> qubit 2w, lanes 16-31 -> qubit 2w+1. Each lane
// covers 32 features (8 float4 pairs); reduce is a 4-stage width-16
// butterfly. Half the threads of the previous version, shorter reduce.

#define NQ 16
#define NF 512
#define NC 10

__global__ __launch_bounds__(256, 4)
void hybrid_fcl_fused(const float* __restrict__ x,
                      const float* __restrict__ enc_w,
                      const float* __restrict__ enc_b,
                      const float* __restrict__ theta,
                      const float* __restrict__ cls_w,
                      const float* __restrict__ cls_b,
                      float* __restrict__ out)
{
    const int b    = blockIdx.x;          // batch row
    const int w    = threadIdx.x >> 5;    // warp id (0..7)
    const int lane = threadIdx.x & 31;
    const int half = lane >> 4;           // 0 or 1
    const int hl   = lane & 15;           // lane within half-warp
    const int q    = 2 * w + half;        // gate-qubit owned by this half-warp
    const int tid  = threadIdx.x;

    // ---- prefetch epilogue constants (overlap the x DRAM/L2 miss) ----
    float4 cw0, cw1, cw2, cw3;
    float  cb = 0.0f;
    if (tid < NC) {
        const float4* cwr = reinterpret_cast<const float4*>(cls_w + tid * NQ);
        cw0 = cwr[0]; cw1 = cwr[1]; cw2 = cwr[2]; cw3 = cwr[3];
        cb  = cls_b[tid];
    }

    // ---- prefetch half-warp-leader constants + hoist cos(Theta) ----
    float cosTh = 0.0f, eb = 0.0f;
    if (hl == 0) {
        eb = enc_b[q];
        float Th = theta[q] + theta[NQ + q] + theta[2 * NQ + q] + theta[3 * NQ + q];
        cosTh = __cosf(Th);
    }

    // ---- 512-feature dot: 8 float4 per lane, 16 lanes per qubit ----
    const float4* __restrict__ xr = reinterpret_cast<const float4*>(x + (size_t)b * NF);
    const float4* __restrict__ wr = reinterpret_cast<const float4*>(enc_w + (size_t)q * NF);

    float4 a0 = xr[hl];        float4 c0 = wr[hl];
    float4 a1 = xr[hl + 16];   float4 c1 = wr[hl + 16];
    float4 a2 = xr[hl + 32];   float4 c2 = wr[hl + 32];
    float4 a3 = xr[hl + 48];   float4 c3 = wr[hl + 48];
    float4 a4 = xr[hl + 64];   float4 c4 = wr[hl + 64];
    float4 a5 = xr[hl + 80];   float4 c5 = wr[hl + 80];
    float4 a6 = xr[hl + 96];   float4 c6 = wr[hl + 96];
    float4 a7 = xr[hl + 112];  float4 c7 = wr[hl + 112];

    // four independent accumulator chains (depth 8 each)
    float p0 = 0.f, p1 = 0.f, p2 = 0.f, p3 = 0.f;
    p0 = fmaf(a0.x, c0.x, p0); p1 = fmaf(a0.y, c0.y, p1);
    p2 = fmaf(a0.z, c0.z, p2); p3 = fmaf(a0.w, c0.w, p3);
    p0 = fmaf(a1.x, c1.x, p0); p1 = fmaf(a1.y, c1.y, p1);
    p2 = fmaf(a1.z, c1.z, p2); p3 = fmaf(a1.w, c1.w, p3);
    p0 = fmaf(a2.x, c2.x, p0); p1 = fmaf(a2.y, c2.y, p1);
    p2 = fmaf(a2.z, c2.z, p2); p3 = fmaf(a2.w, c2.w, p3);
    p0 = fmaf(a3.x, c3.x, p0); p1 = fmaf(a3.y, c3.y, p1);
    p2 = fmaf(a3.z, c3.z, p2); p3 = fmaf(a3.w, c3.w, p3);
    p0 = fmaf(a4.x, c4.x, p0); p1 = fmaf(a4.y, c4.y, p1);
    p2 = fmaf(a4.z, c4.z, p2); p3 = fmaf(a4.w, c4.w, p3);
    p0 = fmaf(a5.x, c5.x, p0); p1 = fmaf(a5.y, c5.y, p1);
    p2 = fmaf(a5.z, c5.z, p2); p3 = fmaf(a5.w, c5.w, p3);
    p0 = fmaf(a6.x, c6.x, p0); p1 = fmaf(a6.y, c6.y, p1);
    p2 = fmaf(a6.z, c6.z, p2); p3 = fmaf(a6.w, c6.w, p3);
    p0 = fmaf(a7.x, c7.x, p0); p1 = fmaf(a7.y, c7.y, p1);
    p2 = fmaf(a7.z, c7.z, p2); p3 = fmaf(a7.w, c7.w, p3);
    float acc = (p0 + p1) + (p2 + p3);

    // 4-stage butterfly within each 16-lane half-warp
#pragma unroll
    for (int off = 8; off; off >>= 1)
        acc += __shfl_xor_sync(0xFFFFFFFFu, acc, off);

    __shared__ float m[NQ];
    if (hl == 0)
        m[q] = cosTh * __cosf(acc + eb);   // single MUFU on the post-reduce path
    __syncthreads();

    // ---- 10 logits, cls_w/cls_b already in registers ----
    if (tid < NC) {
        const float4* ms = reinterpret_cast<const float4*>(m);
        float4 m0 = ms[0], m1 = ms[1], m2 = ms[2], m3 = ms[3];
        float s = cb;   // logits[c] = cb + sum_j m[j] * cls_w[c, 15-j]
        s = fmaf(m0.x, cw3.w, s); s = fmaf(m0.y, cw3.z, s);
        s = fmaf(m0.z, cw3.y, s); s = fmaf(m0.w, cw3.x, s);
        s = fmaf(m1.x, cw2.w, s); s = fmaf(m1.y, cw2.z, s);
        s = fmaf(m1.z, cw2.y, s); s = fmaf(m1.w, cw2.x, s);
        s = fmaf(m2.x, cw1.w, s); s = fmaf(m2.y, cw1.z, s);
        s = fmaf(m2.z, cw1.y, s); s = fmaf(m2.w, cw1.x, s);
        s = fmaf(m3.x, cw0.w, s); s = fmaf(m3.y, cw0.z, s);
        s = fmaf(m3.z, cw0.y, s); s = fmaf(m3.w, cw0.x, s);
        out[(size_t)b * NC + tid] = s;
    }
}

extern "C" void kernel_launch(void* const* d_in, const int* in_sizes, int n_in,
                              void* d_out, int out_size)
{
    const float* x     = (const float*)d_in[0]; // (256, 512)
    const float* enc_w = (const float*)d_in[1]; // (16, 512)
    const float* enc_b = (const float*)d_in[2]; // (16,)
    const float* theta = (const float*)d_in[3]; // (64,)
    const float* cls_w = (const float*)d_in[4]; // (10, 16)
    const float* cls_b = (const float*)d_in[5]; // (10,)
    float* out = (float*)d_out;                 // (256, 10)

    const int batch = in_sizes[0] / NF;         // 256
    hybrid_fcl_fused<<<batch, 256>>>(x, enc_w, enc_b, theta, cls_w, cls_b, out);
}